// round 7
// baseline (speedup 1.0000x reference)
#include <cuda_runtime.h>
#include <cstdint>
#include <cstddef>

// Problem constants
#define TT   255
#define BB   256
#define KK   784
#define NN   40
#define MM   (TT * BB)          // 65280
#define PLANE (BB * NN)         // 10240 elements per timestep
#define OUT_HALF (TT * PLANE)   // 2,611,200

// Scratch for cur = x @ W^T   (10.44 MB, static device global: allowed)
__device__ float g_cur[(size_t)MM * NN];

// packed f32x2 FMA: d = fma(a, b, d) per lane (IEEE rn, fused)
__device__ __forceinline__ void fma2(unsigned long long& d,
                                     unsigned long long a,
                                     unsigned long long b) {
    asm("fma.rn.f32x2 %0, %1, %2, %3;" : "=l"(d) : "l"(a), "l"(b), "l"(d));
}
// packed f32x2 add (rn)
__device__ __forceinline__ unsigned long long add2(unsigned long long a,
                                                   unsigned long long b) {
    unsigned long long d;
    asm("add.rn.f32x2 %0, %1, %2;" : "=l"(d) : "l"(a), "l"(b));
    return d;
}

// ---------------------------------------------------------------------------
// Kernel 1: cur[m][n] = sum_k x[m][k] * W[n][k]
// Accumulation structure emulates SIMD-across-K (NEON V=4, unroll U=2):
//   8 interleaved chains: chain j sums k ≡ j (mod 8), ascending, fused FMA.
//   Combine (faddp pairwise tree):
//     final = ((c0+c4)+(c1+c5)) + ((c2+c6)+(c3+c7))
// K = 784 = 8 * 98 exactly (no tail).
// Grid: 510 blocks (BM=128), 256 threads. Thread tile: 4 rows (2 f32x2
// pairs) x 5 cols, 8 chains each -> 80 packed accumulators.
// ---------------------------------------------------------------------------
__global__ __launch_bounds__(256, 1)
void snn_gemm_kernel(const float* __restrict__ x, const float* __restrict__ W) {
    __shared__ float  As[16][128];      // 8 KB, [k][m]
    __shared__ float2 Ws2[16][40];      // 5 KB, duplicated W pairs

    const int tid  = threadIdx.x;
    const int tcol = tid & 7;           // 8 column-groups * TN=5 -> N=40
    const int trow = tid >> 3;          // 32 row-groups   * TM=4 -> M=128
    const int mbase = blockIdx.x * 128;

    // acc[c][j]: col c (0..4), chain j (0..7); p = rows (4t,4t+1), q = (4t+2,4t+3)
    unsigned long long ap[5][8], aq[5][8];
    #pragma unroll
    for (int c = 0; c < 5; ++c)
        #pragma unroll
        for (int j = 0; j < 8; ++j) { ap[c][j] = 0ULL; aq[c][j] = 0ULL; }

    for (int k0 = 0; k0 < KK; k0 += 16) {
        __syncthreads();   // previous chunk's compute done before overwrite

        // Load A tile: 128 rows x 16 k. 4 threads cover one row (coalesced).
        #pragma unroll
        for (int p = 0; p < 2; ++p) {
            int idx = tid + p * 256;    // < 512
            int row = idx >> 2;
            int q   = idx & 3;
            float4 v = *reinterpret_cast<const float4*>(
                x + (size_t)(mbase + row) * KK + k0 + q * 4);
            As[q * 4 + 0][row] = v.x;
            As[q * 4 + 1][row] = v.y;
            As[q * 4 + 2][row] = v.z;
            As[q * 4 + 3][row] = v.w;
        }

        // Load W tile: 40 n x 16 k, duplicated into float2
        #pragma unroll
        for (int p = 0; p < 3; ++p) {
            int idx = tid + p * 256;
            if (idx < 640) {
                int n  = idx >> 4;
                int kk = idx & 15;
                float w = W[n * KK + k0 + kk];
                Ws2[kk][n] = make_float2(w, w);
            }
        }
        __syncthreads();

        #pragma unroll
        for (int k = 0; k < 16; ++k) {
            const int j = k & 7;        // chain index (k0 is a multiple of 16)
            // One LDS.128: 4 consecutive rows -> 2 packed pairs
            ulonglong2 A = *reinterpret_cast<const ulonglong2*>(&As[k][trow * 4]);
            #pragma unroll
            for (int c = 0; c < 5; ++c) {
                unsigned long long b = *reinterpret_cast<const unsigned long long*>(
                    &Ws2[k][tcol * 5 + c]);
                fma2(ap[c][j], A.x, b);
                fma2(aq[c][j], A.y, b);
            }
        }
    }

    // Combine chains with the pairwise tree, then store
    #pragma unroll
    for (int c = 0; c < 5; ++c) {
        unsigned long long fp, fq;
        {
            unsigned long long t0 = add2(ap[c][0], ap[c][4]);
            unsigned long long t1 = add2(ap[c][1], ap[c][5]);
            unsigned long long t2 = add2(ap[c][2], ap[c][6]);
            unsigned long long t3 = add2(ap[c][3], ap[c][7]);
            fp = add2(add2(t0, t1), add2(t2, t3));
        }
        {
            unsigned long long t0 = add2(aq[c][0], aq[c][4]);
            unsigned long long t1 = add2(aq[c][1], aq[c][5]);
            unsigned long long t2 = add2(aq[c][2], aq[c][6]);
            unsigned long long t3 = add2(aq[c][3], aq[c][7]);
            fq = add2(add2(t0, t1), add2(t2, t3));
        }
        const int n  = tcol * 5 + c;
        const int m0 = mbase + trow * 4;
        g_cur[(size_t)(m0 + 0) * NN + n] = __uint_as_float((unsigned int)(fp & 0xFFFFFFFFu));
        g_cur[(size_t)(m0 + 1) * NN + n] = __uint_as_float((unsigned int)(fp >> 32));
        g_cur[(size_t)(m0 + 2) * NN + n] = __uint_as_float((unsigned int)(fq & 0xFFFFFFFFu));
        g_cur[(size_t)(m0 + 3) * NN + n] = __uint_as_float((unsigned int)(fq >> 32));
    }
}

// ---------------------------------------------------------------------------
// Kernel 2: LIF recurrence over t for each of 10240 (b, n) cells.
//   reset = (mem_prev > 1); mem = (0.95*mem_prev + cur) * (1 - reset);
//   spk = (mem - 1 > 0)  [== mem > 1, sign-exact via Sterbenz]
// mul+add kept un-fused (__fmul_rn/__fadd_rn), CPU-codegen-consistent.
// Ring-buffer prefetch (depth 16) hides L2 latency on the per-t loads.
// ---------------------------------------------------------------------------
__global__ __launch_bounds__(128)
void snn_scan_kernel(float* __restrict__ out) {
    const int idx = blockIdx.x * 128 + threadIdx.x;   // < 10240
    const float* __restrict__ cp = g_cur + idx;
    float* __restrict__ sp = out + idx;               // spk_rec
    float* __restrict__ mp = out + OUT_HALF + idx;    // mem_rec

    float buf[16];
    #pragma unroll
    for (int i = 0; i < 16; ++i) buf[i] = cp[(size_t)i * PLANE];

    float m = 0.0f;

    for (int t0 = 0; t0 < 240; t0 += 16) {
        #pragma unroll
        for (int u = 0; u < 16; ++u) {
            int t = t0 + u;
            float c = buf[u];
            int tn = t + 16; if (tn > TT - 1) tn = TT - 1;
            buf[u] = cp[(size_t)tn * PLANE];
            float r = (m > 1.0f) ? 0.0f : 1.0f;
            m = __fmul_rn(__fadd_rn(__fmul_rn(0.95f, m), c), r);
            sp[(size_t)t * PLANE] = (m > 1.0f) ? 1.0f : 0.0f;
            mp[(size_t)t * PLANE] = m;
        }
    }
    #pragma unroll
    for (int u = 0; u < 15; ++u) {
        int t = 240 + u;
        float c = buf[u];
        float r = (m > 1.0f) ? 0.0f : 1.0f;
        m = __fmul_rn(__fadd_rn(__fmul_rn(0.95f, m), c), r);
        sp[(size_t)t * PLANE] = (m > 1.0f) ? 1.0f : 0.0f;
        mp[(size_t)t * PLANE] = m;
    }
}

// ---------------------------------------------------------------------------
extern "C" void kernel_launch(void* const* d_in, const int* in_sizes, int n_in,
                              void* d_out, int out_size) {
    const float* x = (const float*)d_in[0];
    const float* W = (const float*)d_in[1];
    // Defensive: metadata order should be (x, W); swap if sizes say otherwise.
    if (n_in >= 2 && in_sizes[0] == NN * KK) {
        const float* t = x; x = W; W = t;
    }
    float* out = (float*)d_out;

    snn_gemm_kernel<<<MM / 128, 256>>>(x, W);   // 510 blocks
    snn_scan_kernel<<<PLANE / 128, 128>>>(out); // 80 blocks
}